// round 4
// baseline (speedup 1.0000x reference)
#include <cuda_runtime.h>

#define BB 128
#define TT 256
#define KDIM 50
#define KK 2500          // K*K
#define START_TAG 48
#define END_TAG 49
#define NTH 256
#define NLOADER 192
#define SLACK 32.0f

__device__ float g_apart[BB];   // per-sequence log all-paths (natural log)
__device__ float g_gpart[BB];   // per-sequence gold partial
__device__ int   g_count = 0;   // last-block counter (self-resetting)

struct Smem {
    float raw[5][KK];      // cp.async landing slots (raw scores)
    float pt[2][KK];       // transposed exp2 tiles: pt[buf][k*50 + j]
    float wbuf[2][64];     // alpha weights (double buffered)
    float r0s[2];          // r[0] broadcast (double buffered)
    int   tg[TT];
    float sred[8];
    float sA;
    int   sflag;
    float sa[4], sg[4];
};

__device__ __forceinline__ void cp16(void* dst_smem, const void* src) {
    unsigned s = (unsigned)__cvta_generic_to_shared(dst_smem);
    asm volatile("cp.async.cg.shared.global [%0], [%1], 16;\n" :: "r"(s), "l"(src));
}
__device__ __forceinline__ void cp_commit() {
    asm volatile("cp.async.commit_group;\n");
}
template <int N>
__device__ __forceinline__ void cp_wait() {
    asm volatile("cp.async.wait_group %0;\n" :: "n"(N));
}
__device__ __forceinline__ float ex2f(float x) {
    float y; asm("ex2.approx.f32 %0, %1;" : "=f"(y) : "f"(x)); return y;
}
__device__ __forceinline__ float lg2f(float x) {
    float y; asm("lg2.approx.f32 %0, %1;" : "=f"(y) : "f"(x)); return y;
}

__global__ __launch_bounds__(NTH, 1)
void viterbi_ws_kernel(const float* __restrict__ scores,
                       const int* __restrict__ targets,
                       const int* __restrict__ lengths,
                       float* __restrict__ out) {
    extern __shared__ __align__(16) char smem_raw[];
    Smem& S = *reinterpret_cast<Smem*>(smem_raw);

    const int b    = blockIdx.x;
    const int tid  = threadIdx.x;
    const int wid  = tid >> 5;
    const int lane = tid & 31;
    const int len  = lengths[b];
    const float* base = scores + (size_t)b * TT * KK;
    const float L = 1.4426950408889634f;   // log2(e)

    S.tg[tid] = targets[b * TT + tid];

    const bool isLoader = (tid >= 64);
    const int  k = tid;                     // compute column (valid < 50)

    // convert ranges per loader warp (w4/w5 doubled to balance MUFU across SMSPs)
    int ws = 0, we = 0;
    if (isLoader) {
        const int starts[7] = {0, 312, 624, 1249, 1874, 2187, 2500};
        ws = starts[wid - 2];
        we = starts[wid - 1];
    }

    auto issue = [&](int t) {               // loaders only
        if (isLoader) {
            if (t < len) {
                const float4* src = (const float4*)(base + (size_t)t * KK);
                float4* dst = (float4*)(S.raw[t % 5]);
                int ltid = tid - 64;
                #pragma unroll
                for (int i = 0; i < 4; ++i) {
                    int c = ltid + i * NLOADER;
                    if (c < 625) cp16(dst + c, src + c);
                }
            }
            cp_commit();                    // always commit: static group counts
        }
    };

    float gold = 0.f;
    auto convert = [&](int t) {             // raw[t%5] -> pt[t&1] transposed, + gold
        const float* rp = S.raw[t % 5];
        float* pp = S.pt[t & 1];
        const int tgt = S.tg[t];
        int e = ws + lane;
        int j = e / KDIM, kk = e - j * KDIM;
        for (; e < we; e += 32) {
            float v = rp[e];
            if (e == tgt) gold += v;        // gather raw before exp
            pp[kk * KDIM + j] = ex2f(v * L);
            kk += 32; if (kk >= KDIM) { kk -= KDIM; ++j; }
        }
    };

    // ---- prologue: issue tiles 0..3, certify 0,1 ----
    issue(0); issue(1); issue(2); issue(3);
    if (isLoader) cp_wait<2>();
    __syncthreads();

    float r = 0.f, shiftsum = 0.f, dnext = 0.f;

    // ---- phase 0 ----
    if (!isLoader) {
        if (k < KDIM) {
            float s0 = S.raw[0][START_TAG * KDIM + k];
            float a0 = S.raw[0][START_TAG * KDIM];      // broadcast anchor r0[0]
            r = s0 * L;
            dnext = __fmaf_rn(a0, L, SLACK);            // delta_1
            S.wbuf[1][k] = ex2f(r - dnext);
            if (k == 0) S.r0s[0] = r;
        }
    } else {
        issue(4);
        cp_wait<2>();                                   // certify tile 2
        if (tid == 64) gold += S.raw[0][S.tg[0]];       // gold t=0 from raw
        if (1 < len) convert(1);
    }
    __syncthreads();

    // ---- main phases: compute GEMV(t) || loader convert(t+1) + issue(t+4) ----
    for (int t = 1; t < len; ++t) {
        if (!isLoader) {
            if (k < KDIM) {
                const float2* wp = (const float2*)S.wbuf[t & 1];
                float2 wv[25];
                #pragma unroll
                for (int j = 0; j < 25; ++j) wv[j] = wp[j];
                const float2* pp2 = (const float2*)(S.pt[t & 1] + k * KDIM);
                float s0 = 0.f, s1 = 0.f, s2 = 0.f, s3 = 0.f;
                #pragma unroll
                for (int j = 0; j < 25; ++j) {
                    float2 p = pp2[j];
                    if (j & 1) { s2 = __fmaf_rn(wv[j].x, p.x, s2);
                                 s3 = __fmaf_rn(wv[j].y, p.y, s3); }
                    else       { s0 = __fmaf_rn(wv[j].x, p.x, s0);
                                 s1 = __fmaf_rn(wv[j].y, p.y, s1); }
                }
                shiftsum += dnext;                       // consume delta_t
                r = lg2f((s0 + s2) + (s1 + s3));
                float dn = S.r0s[(t - 1) & 1] + SLACK;   // delta_{t+1} = r_{t-1}[0]+SLACK
                S.wbuf[(t + 1) & 1][k] = ex2f(r - dn);
                dnext = dn;
                if (k == 0) S.r0s[t & 1] = r;
            }
        } else {
            issue(t + 4);                                // slot (t-1)%5: tile t-1 done
            cp_wait<2>();                                // certify tile t+2
            if (t + 1 < len) convert(t + 1);             // certified last phase
        }
        __syncthreads();
    }

    // ---- epilogue: gold reduce (all warps) + per-seq outputs ----
    float gs = gold;
    #pragma unroll
    for (int o = 16; o > 0; o >>= 1) gs += __shfl_xor_sync(0xFFFFFFFFu, gs, o);
    if (lane == 0) S.sred[wid] = gs;
    if (tid == END_TAG) S.sA = (shiftsum + r) * 0.6931471805599453f;
    __syncthreads();
    if (tid == 0) {
        float G = 0.f;
        #pragma unroll
        for (int i = 0; i < 8; ++i) G += S.sred[i];
        g_gpart[b] = G;
        g_apart[b] = S.sA;
        __threadfence();
        int old = atomicAdd(&g_count, 1);
        S.sflag = (old == BB - 1) ? 1 : 0;
    }
    __syncthreads();

    if (S.sflag) {                                       // last block: final reduce
        __threadfence();
        float a = 0.f, gd = 0.f;
        if (tid < BB) { a = g_apart[tid]; gd = g_gpart[tid]; }
        #pragma unroll
        for (int o = 16; o > 0; o >>= 1) {
            a  += __shfl_down_sync(0xFFFFFFFFu, a, o);
            gd += __shfl_down_sync(0xFFFFFFFFu, gd, o);
        }
        if (tid < BB && (tid & 31) == 0) { S.sa[tid >> 5] = a; S.sg[tid >> 5] = gd; }
        __syncthreads();
        if (tid == 0) {
            float A = S.sa[0] + S.sa[1] + S.sa[2] + S.sa[3];
            float G = S.sg[0] + S.sg[1] + S.sg[2] + S.sg[3];
            out[0] = (A - G) / (float)BB;
            atomicExch(&g_count, 0);                     // reset for graph replay
        }
    }
}

extern "C" void kernel_launch(void* const* d_in, const int* in_sizes, int n_in,
                              void* d_out, int out_size) {
    const float* scores  = (const float*)d_in[0];
    const int*   targets = (const int*)d_in[1];
    const int*   lengths = (const int*)d_in[2];
    // d_in[3] = tmap_correct (unused scalar)
    cudaFuncSetAttribute(viterbi_ws_kernel,
                         cudaFuncAttributeMaxDynamicSharedMemorySize,
                         (int)sizeof(Smem));
    viterbi_ws_kernel<<<BB, NTH, sizeof(Smem)>>>(scores, targets, lengths,
                                                 (float*)d_out);
}

// round 5
// speedup vs baseline: 2.3147x; 2.3147x over previous
#include <cuda_runtime.h>

#define BB 128
#define TT 256
#define KDIM 50
#define KK 2500          // K*K
#define START_TAG 48
#define END_TAG 49
#define NTH 256
#define SLACK 24.0f

__device__ float g_apart[BB];   // per-seq log all-paths (natural log)
__device__ float g_gpart[BB];   // per-seq gold partial
__device__ int   g_count = 0;   // last-block counter (self-resetting)

__device__ __forceinline__ void cp8(void* dst_smem, const void* src) {
    unsigned s = (unsigned)__cvta_generic_to_shared(dst_smem);
    asm volatile("cp.async.ca.shared.global [%0], [%1], 8;\n" :: "r"(s), "l"(src));
}
__device__ __forceinline__ void cp_commit() {
    asm volatile("cp.async.commit_group;\n");
}
template <int N>
__device__ __forceinline__ void cp_wait() {
    asm volatile("cp.async.wait_group %0;\n" :: "n"(N));
}
__device__ __forceinline__ float ex2f(float x) {
    float y; asm("ex2.approx.f32 %0, %1;" : "=f"(y) : "f"(x)); return y;
}
__device__ __forceinline__ float lg2f(float x) {
    float y; asm("lg2.approx.f32 %0, %1;" : "=f"(y) : "f"(x)); return y;
}
__device__ __forceinline__ void group_bar(int g) {   // 2-warp named barrier
    asm volatile("bar.sync %0, %1;" :: "r"(g + 1), "r"(64) : "memory");
}

__global__ __launch_bounds__(NTH, 1)
void viterbi_gb_kernel(const float* __restrict__ scores,
                       const int* __restrict__ targets,
                       const int* __restrict__ lengths,
                       float* __restrict__ out) {
    __shared__ __align__(16) float raw[4][KK];   // quad-buffered raw tiles (40 KB)
    __shared__ float red2[2][4][64];             // per-group partials, double buffered
    __shared__ float abuf[4][64];                // group-PRIVATE shifted log2-alpha
    __shared__ float r0buf[2][4];                // r[0] anchor per group, double buffered
    __shared__ int   strow[TT], stcol[TT];
    __shared__ float sred[8];
    __shared__ float sAsh;
    __shared__ int   sflag;
    __shared__ float sa[4], sg[4];

    const int b    = blockIdx.x;
    const int tid  = threadIdx.x;
    const int wid  = tid >> 5;
    const int lane = tid & 31;
    const int g    = tid >> 6;    // group 0..3 owns rows j == g (mod 4)
    const int k    = tid & 63;    // column lane (active < 50)
    const int tig  = tid & 63;    // index within group for loading
    const int len  = lengths[b];
    const float* base = scores + (size_t)b * TT * KK;
    const float L = 1.4426950408889634f;   // log2(e)

    {   // target row/col precompute
        int tv = targets[b * TT + tid];
        int tr = tv / KDIM;
        strow[tid] = tr;
        stcol[tid] = tv - tr * KDIM;
    }

    const int nch = (g < 2) ? 325 : 300;   // 13 or 12 rows x 25 x 8B chunks

    auto issue = [&](int t) {
        if (t < len) {
            const float* src = base + (size_t)t * KK;
            float* dst = raw[t & 3];
            #pragma unroll
            for (int i = 0; i < 6; ++i) {
                int c = tig + i * 64;
                if (c < nch) {
                    int rowi = c / 25;
                    int rem  = c - rowi * 25;
                    int off  = (g + 4 * rowi) * KDIM + rem * 2;
                    cp8(dst + off, src + off);
                }
            }
        }
        cp_commit();                         // always: static group accounting
    };

    issue(0); issue(1); issue(2); issue(3);
    cp_wait<2>();                            // tiles 0,1 landed (own chunks)
    __syncthreads();                         // full certification of tiles 0,1

    float gold = 0.f, r = 0.f, rshift = 0.f, abshift = 0.f;

    // ---- prologue (t=0): alpha from START row; every group builds its abuf ----
    if (k < KDIM) {
        r = raw[0][START_TAG * KDIM + k] * L;
        float r0b = raw[0][START_TAG * KDIM] * L;   // broadcast anchor
        float d = r0b + SLACK;
        abuf[g][k] = r - d;
        abshift = d;                          // shift embedded in abuf
        if (k == 0) r0buf[0][g] = r;
        int trow = strow[0], tcol = stcol[0];
        if (((trow & 3) == g) && (k == tcol)) gold += raw[0][trow * KDIM + tcol];
    } else {
        abuf[g][k] = -1e30f;                  // j >= 50 slots -> exp2 -> 0
    }

    for (int t = 1; t < len; ++t) {
        group_bar(g);                         // own-group abuf + tile-t rows ready

        // ---- pass1: partial sums over this group's rows ----
        if (k < KDIM) {
            const float* sb = raw[t & 3];
            const float* ab = abuf[g];
            float s0 = 0.f, s1 = 0.f, s2 = 0.f, s3 = 0.f;
            #pragma unroll
            for (int i = 0; i < 13; ++i) {
                int j  = g + 4 * i;
                int jj = (j < KDIM) ? j : 0;
                float e = ex2f(__fmaf_rn(sb[jj * KDIM + k], L, ab[j]));
                if      ((i & 3) == 0) s0 += e;
                else if ((i & 3) == 1) s1 += e;
                else if ((i & 3) == 2) s2 += e;
                else                   s3 += e;
            }
            red2[t & 1][g][k] = (s0 + s2) + (s1 + s3);
            int trow = strow[t], tcol = stcol[t];
            if (((trow & 3) == g) && (k == tcol)) gold += sb[trow * KDIM + tcol];
        }
        __syncthreads();                      // red2 visible to all groups

        issue(t + 3);                         // into slot (t-1)&3 (fully drained)

        // ---- redundant tail: every group computes all 50 columns ----
        if (k < KDIM) {
            float tot = red2[t & 1][0][k] + red2[t & 1][1][k]
                      + red2[t & 1][2][k] + red2[t & 1][3][k];
            float rn = lg2f(tot);
            rshift = abshift;                 // shift embedded in rn
            float d = r0buf[(t - 1) & 1][g] + SLACK;
            abuf[g][k] = rn - d;
            abshift = rshift + d;
            if (k == 0) r0buf[t & 1][g] = rn;
            r = rn;
        }
        cp_wait<2>();                         // certify tile t+1 (own chunks)
    }

    // ---- epilogue ----
    float gs = gold;
    #pragma unroll
    for (int o = 16; o > 0; o >>= 1) gs += __shfl_xor_sync(0xFFFFFFFFu, gs, o);
    if (lane == 0) sred[wid] = gs;
    if (tid == END_TAG) sAsh = (r + rshift) * 0.6931471805599453f; // tid49 = (g0,k=END)
    __syncthreads();
    if (tid == 0) {
        float G = 0.f;
        #pragma unroll
        for (int i = 0; i < 8; ++i) G += sred[i];
        g_gpart[b] = G;
        g_apart[b] = sAsh;
        __threadfence();
        int old = atomicAdd(&g_count, 1);
        sflag = (old == BB - 1) ? 1 : 0;
    }
    __syncthreads();

    if (sflag) {                              // last block: deterministic final reduce
        __threadfence();
        float a = 0.f, gd = 0.f;
        if (tid < BB) { a = g_apart[tid]; gd = g_gpart[tid]; }
        #pragma unroll
        for (int o = 16; o > 0; o >>= 1) {
            a  += __shfl_down_sync(0xFFFFFFFFu, a, o);
            gd += __shfl_down_sync(0xFFFFFFFFu, gd, o);
        }
        if ((lane == 0) && (tid < BB)) { sa[wid] = a; sg[wid] = gd; }
        __syncthreads();
        if (tid == 0) {
            float A = sa[0] + sa[1] + sa[2] + sa[3];
            float G = sg[0] + sg[1] + sg[2] + sg[3];
            out[0] = (A - G) / (float)BB;
            atomicExch(&g_count, 0);          // reset for next graph replay
        }
    }
}

extern "C" void kernel_launch(void* const* d_in, const int* in_sizes, int n_in,
                              void* d_out, int out_size) {
    const float* scores  = (const float*)d_in[0];
    const int*   targets = (const int*)d_in[1];
    const int*   lengths = (const int*)d_in[2];
    // d_in[3] = tmap_correct (unused scalar)
    viterbi_gb_kernel<<<BB, NTH>>>(scores, targets, lengths, (float*)d_out);
}

// round 6
// speedup vs baseline: 3.6186x; 1.5633x over previous
#include <cuda_runtime.h>

#define BB 128
#define TT 256
#define KDIM 50
#define KK 2500          // K*K
#define START_TAG 48
#define END_TAG 49
#define NTH 256
#define SLACK 24.0f

__device__ float g_vec[2][BB][64];   // [dir][seq][tag]: absolute log2 alpha/beta at split
__device__ float g_gold[2][BB];      // gold partial per (dir, seq)
__device__ float g_apart[BB];        // combined per-seq log all-paths (nats)
__device__ float g_gpart[BB];        // combined per-seq gold
__device__ int   g_pair[BB];         // per-pair arrival counters (self-resetting)
__device__ int   g_count = 0;        // global arrival counter (self-resetting)

__device__ __forceinline__ void cp16(void* dst_smem, const void* src) {
    unsigned s = (unsigned)__cvta_generic_to_shared(dst_smem);
    asm volatile("cp.async.cg.shared.global [%0], [%1], 16;\n" :: "r"(s), "l"(src));
}
__device__ __forceinline__ void cp_commit() {
    asm volatile("cp.async.commit_group;\n");
}
template <int N>
__device__ __forceinline__ void cp_wait() {
    asm volatile("cp.async.wait_group %0;\n" :: "n"(N));
}
__device__ __forceinline__ float ex2f(float x) {
    float y; asm("ex2.approx.f32 %0, %1;" : "=f"(y) : "f"(x)); return y;
}
__device__ __forceinline__ float lg2f(float x) {
    float y; asm("lg2.approx.f32 %0, %1;" : "=f"(y) : "f"(x)); return y;
}

__global__ __launch_bounds__(NTH, 2)
void viterbi_split_kernel(const float* __restrict__ scores,
                          const int* __restrict__ targets,
                          const int* __restrict__ lengths,
                          float* __restrict__ out) {
    __shared__ __align__(16) float raw[4][KK];   // quad-buffered raw tiles (40 KB)
    __shared__ float red2[4][64];                // per-group partial sums
    __shared__ float vbuf[64];                   // shifted log2 state vector
    __shared__ float r0s[2];                     // stale anchor r_{v}[0], double buffered
    __shared__ int   tg[TT];
    __shared__ int   sPair, sFin;
    __shared__ float sa[4], sg[4];

    const int bx   = blockIdx.x;
    const int dirB = bx >> 7;            // 0 = forward, 1 = backward
    const int b    = bx & (BB - 1);
    const int tid  = threadIdx.x;
    const int lane = tid & 31;
    const int wid  = tid >> 5;
    const int g    = tid >> 6;           // group 0..3
    const int c    = tid & 63;           // output index (tag), active < 50
    const int len  = lengths[b];
    const int m    = (len + 1) >> 1;
    const int nv   = dirB ? (len - m + 1) : m;   // visits incl. bwd virtual visit 0
    const float* base = scores + (size_t)b * TT * KK;
    const float L = 1.4426950408889634f; // log2(e)

    tg[tid] = targets[b * TT + tid];

    auto issue = [&](int vv) {
        bool real = (vv < nv) && (!dirB || vv >= 1);
        if (real) {
            int t = dirB ? (len - vv) : vv;
            const float4* src = (const float4*)(base + (size_t)t * KK);
            float4* dst = (float4*)raw[vv & 3];
            #pragma unroll
            for (int i = 0; i < 3; ++i) {
                int c4 = tid + i * NTH;
                if (c4 < 625) cp16(dst + c4, src + c4);
            }
        }
        cp_commit();                     // always commit: static group accounting
    };

    issue(0); issue(1); issue(2); issue(3);
    cp_wait<3>();
    __syncthreads();                     // visit 0 certified

    float gold = 0.f, r = 0.f, shift = 0.f, dcur = 0.f;

    // ---- init: state at the starting end ----
    if (!dirB) {
        // alpha_0 from START row of tile 0
        float anchor = raw[0][START_TAG * KDIM] * L;   // broadcast
        dcur = anchor + SLACK;
        if (tid < 64) {
            if (c < KDIM) {
                r = raw[0][START_TAG * KDIM + c] * L;
                vbuf[c] = r - dcur;
            } else vbuf[c] = -1e30f;
            if (c == 0) r0s[0] = r;       // r_init[0] = anchor
        }
        if (tid == 0) gold += raw[0][tg[0]];
    } else {
        // beta_{len-1}: 0 at END, -inf elsewhere; dcur = 0
        dcur = 0.f;
        if (tid < 64) {
            r = (c == END_TAG) ? 0.f : -1e30f;
            vbuf[c] = r;
            if (c == 0) r0s[0] = 0.f;
        }
    }

    for (int v = 1; v < nv; ++v) {
        cp_wait<2>();                    // own chunks of visit v landed
        __syncthreads();                 // barA: tile v + vbuf certified
        issue(v + 3);                    // into slot (v-1)&3 (drained)

        const float* sb = raw[v & 3];
        const int t = dirB ? (len - v) : v;
        if (tid == 0) gold += sb[tg[t]];

        if (c < KDIM) {
            const float* ab = vbuf;
            float s0 = 0.f, s1 = 0.f, s2 = 0.f, s3 = 0.f;
            if (!dirB) {
                // fwd: sum over j == g (mod 4); addr = j*50 + c
                #pragma unroll
                for (int i = 0; i < 13; ++i) {
                    int j  = g + 4 * i;
                    int jj = (j < KDIM) ? j : 0;
                    float e = ex2f(__fmaf_rn(sb[jj * KDIM + c], L, ab[j]));
                    if      ((i & 3) == 0) s0 += e;
                    else if ((i & 3) == 1) s1 += e;
                    else if ((i & 3) == 2) s2 += e;
                    else                   s3 += e;
                }
            } else {
                // bwd: sum over k == g (mod 4); addr = c*50 + k
                #pragma unroll
                for (int i = 0; i < 13; ++i) {
                    int kk  = g + 4 * i;
                    int kkc = (kk < KDIM) ? kk : 0;
                    float e = ex2f(__fmaf_rn(sb[c * KDIM + kkc], L, ab[kk]));
                    if      ((i & 3) == 0) s0 += e;
                    else if ((i & 3) == 1) s1 += e;
                    else if ((i & 3) == 2) s2 += e;
                    else                   s3 += e;
                }
            }
            red2[g][c] = (s0 + s2) + (s1 + s3);
        }
        __syncthreads();                 // barB: red2 ready, vbuf free

        if (tid < 64 && c < KDIM) {      // serial g0 tail
            float tot = red2[0][c] + red2[1][c] + red2[2][c] + red2[3][c];
            r = lg2f(tot);
            shift += dcur;
            float dn = r0s[(v - 1) & 1] + SLACK;   // stale anchor r_{v-1}[0]
            vbuf[c] = r - dn;
            dcur = dn;
            if (c == 0) r0s[v & 1] = r;
        }
    }

    cp_wait<0>();
    __syncthreads();

    // ---- publish half-result ----
    if (tid < 64 && c < KDIM) g_vec[dirB][b][c] = r + shift;   // absolute log2
    if (tid == 0) g_gold[dirB][b] = gold;
    __syncthreads();                     // all stores executed
    if (tid == 0) {
        __threadfence();
        sPair = atomicAdd(&g_pair[b], 1);
    }
    __syncthreads();

    if (sPair == 1) {                    // second arrival: combine the pair
        __threadfence();
        if (tid < 32) {
            int j2 = tid + 32;
            float x1 = g_vec[0][b][tid] + g_vec[1][b][tid];
            float x2 = (j2 < KDIM) ? (g_vec[0][b][j2] + g_vec[1][b][j2]) : -1e30f;
            float mx = fmaxf(x1, x2);
            #pragma unroll
            for (int o = 16; o > 0; o >>= 1)
                mx = fmaxf(mx, __shfl_xor_sync(0xFFFFFFFFu, mx, o));
            float s = ex2f(x1 - mx) + ex2f(x2 - mx);
            #pragma unroll
            for (int o = 16; o > 0; o >>= 1)
                s += __shfl_xor_sync(0xFFFFFFFFu, s, o);
            if (tid == 0) {
                g_apart[b] = (mx + lg2f(s)) * 0.6931471805599453f;
                g_gpart[b] = g_gold[0][b] + g_gold[1][b];
                g_pair[b]  = 0;          // reset for next graph replay
            }
        }
    }
    __syncthreads();
    if (tid == 0) {
        __threadfence();
        int old = atomicAdd(&g_count, 1);
        sFin = (old == 2 * BB - 1) ? 1 : 0;
    }
    __syncthreads();

    if (sFin) {                          // very last CTA: deterministic final reduce
        __threadfence();
        float a = 0.f, gd = 0.f;
        if (tid < BB) { a = g_apart[tid]; gd = g_gpart[tid]; }
        #pragma unroll
        for (int o = 16; o > 0; o >>= 1) {
            a  += __shfl_down_sync(0xFFFFFFFFu, a, o);
            gd += __shfl_down_sync(0xFFFFFFFFu, gd, o);
        }
        if (tid < BB && lane == 0) { sa[wid] = a; sg[wid] = gd; }
        __syncthreads();
        if (tid == 0) {
            float A = sa[0] + sa[1] + sa[2] + sa[3];
            float G = sg[0] + sg[1] + sg[2] + sg[3];
            out[0] = (A - G) / (float)BB;
            atomicExch(&g_count, 0);     // reset for next graph replay
        }
    }
}

extern "C" void kernel_launch(void* const* d_in, const int* in_sizes, int n_in,
                              void* d_out, int out_size) {
    const float* scores  = (const float*)d_in[0];
    const int*   targets = (const int*)d_in[1];
    const int*   lengths = (const int*)d_in[2];
    // d_in[3] = tmap_correct (unused scalar)
    viterbi_split_kernel<<<2 * BB, NTH>>>(scores, targets, lengths, (float*)d_out);
}